// round 1
// baseline (speedup 1.0000x reference)
#include <cuda_runtime.h>

// Problem constants
#define B_  2
#define L_  4096
#define DIN 512
#define H_  8
#define DK  64
#define DV  64
#define DOUT 512

#define NCHUNK 16        // split-K chunks for the gram matrix
#define KC     (L_ / NCHUNK)   // 256

// ---------------- scratch (device globals; no runtime alloc) ----------------
__device__ float g_Gpart[NCHUNK * B_ * 512 * 512]; // split-K partials of X^T X
__device__ float g_G   [B_ * 512 * 512];           // G_b = X_b^T X_b
__device__ float g_T1  [B_ * H_ * 512 * 64];       // T1[b,h] = G_b @ Wv_h
__device__ float g_M2  [B_ * H_ * 64 * 64];        // M2[b,h] = Wk_h^T @ T1
__device__ float g_C2  [B_ * 512 * 512];           // C2[b][i][h*64+v] = (Wq_h @ M2)[i,v]
__device__ float g_R   [B_ * 512 * 512];           // R_b = C2_b @ Wo_flat

// ---------------- generic 64x64 tile SGEMM (BK=16, 256 thr, 4x4 microtile) --
template<bool TRANSA>
__device__ __forceinline__ void gemm_tile64(
    const float* __restrict__ A, const float* __restrict__ B,
    float* __restrict__ C,
    int lda, int ldb, int ldc,
    int m0, int n0, int kbeg, int kend)
{
    __shared__ float As[16][68];   // pad 4 -> 272B rows: 16B-aligned float4 reads
    __shared__ float Bs[16][64];

    const int tid = threadIdx.x;
    const int tx = tid & 15;       // column group
    const int ty = tid >> 4;       // row group

    float acc[4][4];
#pragma unroll
    for (int i = 0; i < 4; i++)
#pragma unroll
        for (int j = 0; j < 4; j++) acc[i][j] = 0.f;

    for (int k0 = kbeg; k0 < kend; k0 += 16) {
#pragma unroll
        for (int i = 0; i < 4; i++) {
            int idx = tid + i * 256;
            if (TRANSA) {
                // A is stored K x M (logical A[m][k] = A[k*lda + m]) — coalesced in m
                int kk = idx >> 6, mm = idx & 63;
                As[kk][mm] = A[(long)(k0 + kk) * lda + m0 + mm];
            } else {
                // A is stored M x K — coalesced runs of 16 along k
                int kk = idx & 15, mm = idx >> 4;
                As[kk][mm] = A[(long)(m0 + mm) * lda + k0 + kk];
            }
            int kk2 = idx >> 6, nn = idx & 63;   // B always K x N, coalesced in n
            Bs[kk2][nn] = B[(long)(k0 + kk2) * ldb + n0 + nn];
        }
        __syncthreads();

#pragma unroll
        for (int kk = 0; kk < 16; kk++) {
            float4 a4 = *(const float4*)&As[kk][ty * 4];
            float4 b4 = *(const float4*)&Bs[kk][tx * 4];
            float av[4] = {a4.x, a4.y, a4.z, a4.w};
            float bv[4] = {b4.x, b4.y, b4.z, b4.w};
#pragma unroll
            for (int i = 0; i < 4; i++)
#pragma unroll
                for (int j = 0; j < 4; j++)
                    acc[i][j] += av[i] * bv[j];
        }
        __syncthreads();
    }

#pragma unroll
    for (int i = 0; i < 4; i++) {
        float4 v = make_float4(acc[i][0], acc[i][1], acc[i][2], acc[i][3]);
        *(float4*)&C[(long)(m0 + ty * 4 + i) * ldc + n0 + tx * 4] = v;
    }
}

// ---------------- stage kernels ----------------

// Gpart[c][b] = X_b[kchunk]^T X_b[kchunk]   (512x512, K=256 per chunk)
__global__ __launch_bounds__(256) void k_gram(const float* __restrict__ x)
{
    int b = blockIdx.z / NCHUNK;
    int c = blockIdx.z % NCHUNK;
    const float* X = x + (long)b * L_ * DIN;
    float* out = g_Gpart + ((long)c * B_ + b) * 512 * 512;
    gemm_tile64<true>(X, X, out, DIN, DIN, 512,
                      blockIdx.x * 64, blockIdx.y * 64, c * KC, c * KC + KC);
}

// G = sum over chunks of Gpart
__global__ __launch_bounds__(256) void k_greduce()
{
    int i = blockIdx.x * 256 + threadIdx.x;  // B_*512*512 = 524288 total
    float s = 0.f;
#pragma unroll
    for (int c = 0; c < NCHUNK; c++)
        s += g_Gpart[(long)c * (B_ * 512 * 512) + i];
    g_G[i] = s;
}

// T1[b,h] = G_b @ Wv_h   (512x64, K=512)
__global__ __launch_bounds__(256) void k_t1(const float* __restrict__ Wv)
{
    int bh = blockIdx.z, b = bh >> 3, h = bh & 7;
    gemm_tile64<false>(g_G + (long)b * 512 * 512,
                       Wv + (long)h * DIN * DV,
                       g_T1 + (long)bh * 512 * 64,
                       512, DV, 64,
                       blockIdx.x * 64, 0, 0, 512);
}

// M2[b,h] = Wk_h^T @ T1[b,h]   (64x64, K=512)
__global__ __launch_bounds__(256) void k_m2(const float* __restrict__ Wk)
{
    int bh = blockIdx.z, h = bh & 7;
    gemm_tile64<true>(Wk + (long)h * DIN * DK,      // stored K x M (512 x 64)
                      g_T1 + (long)bh * 512 * 64,
                      g_M2 + (long)bh * 64 * 64,
                      DK, 64, 64,
                      0, 0, 0, 512);
}

// C2[b][i][h*64+v] = (Wq_h @ M2[b,h])[i,v]   (512x64, K=64)
__global__ __launch_bounds__(256) void k_cmat(const float* __restrict__ Wq)
{
    int bh = blockIdx.z, b = bh >> 3, h = bh & 7;
    gemm_tile64<false>(Wq + (long)h * DIN * DK,
                       g_M2 + (long)bh * 64 * 64,
                       g_C2 + (long)b * 512 * 512 + h * 64,
                       DK, 64, 512,
                       blockIdx.x * 64, 0, 0, 64);
}

// R_b = C2_b @ Wo_flat   (512x512, K=512). Wo (H,DV,DOUT) flattens to (512,512).
__global__ __launch_bounds__(256) void k_r(const float* __restrict__ Wo)
{
    int b = blockIdx.z;
    gemm_tile64<false>(g_C2 + (long)b * 512 * 512,
                       Wo,
                       g_R + (long)b * 512 * 512,
                       512, DOUT, 512,
                       blockIdx.x * 64, blockIdx.y * 64, 0, 512);
}

// out_b = X_b @ R_b   (4096x512, K=512)
__global__ __launch_bounds__(256) void k_out(const float* __restrict__ x,
                                             float* __restrict__ out)
{
    int b = blockIdx.z;
    gemm_tile64<false>(x + (long)b * L_ * DIN,
                       g_R + (long)b * 512 * 512,
                       out + (long)b * L_ * DOUT,
                       DIN, 512, DOUT,
                       blockIdx.x * 64, blockIdx.y * 64, 0, 512);
}

// ---------------- launch ----------------
extern "C" void kernel_launch(void* const* d_in, const int* in_sizes, int n_in,
                              void* d_out, int out_size)
{
    const float* x  = (const float*)d_in[0];   // (2, 4096, 512)
    const float* Wq = (const float*)d_in[1];   // (8, 512, 64)
    const float* Wk = (const float*)d_in[2];   // (8, 512, 64)
    const float* Wv = (const float*)d_in[3];   // (8, 512, 64)
    const float* Wo = (const float*)d_in[4];   // (8, 64, 512)
    float* out = (float*)d_out;                // (2, 4096, 512)

    k_gram   <<<dim3(8, 8, B_ * NCHUNK), 256>>>(x);
    k_greduce<<<(B_ * 512 * 512) / 256, 256>>>();
    k_t1     <<<dim3(8, 1, B_ * H_), 256>>>(Wv);
    k_m2     <<<dim3(1, 1, B_ * H_), 256>>>(Wk);
    k_cmat   <<<dim3(8, 1, B_ * H_), 256>>>(Wq);
    k_r      <<<dim3(8, 8, B_), 256>>>(Wo);
    k_out    <<<dim3(64, 8, B_), 256>>>(x, out);
}

// round 4
// speedup vs baseline: 1.2093x; 1.2093x over previous
#include <cuda_runtime.h>

#define B_   2
#define L_   4096
#define DIN  512
#define H_   8
#define DK   64
#define DV   64
#define DOUT 512

#define NCH_G 8      // split-K chunks for gram (K=4096 -> 512 each)
#define NCH_M 8      // split-K chunks for middle GEMMs (K=512 -> 64 each)
#define SZ   (512 * 512)         // one 512x512 matrix
#define NTOT (B_ * SZ)           // per-batch pair

// ---------------- scratch ----------------
__device__ float g_Gp [NCH_G * NTOT];   // gram split-K partials
__device__ float g_Pb [NCH_M * NTOT];   // shared split-K partials for middle GEMMs
__device__ float g_G  [NTOT];           // G_b = X_b^T X_b
__device__ float g_T1 [NTOT];           // T1cat = G_b @ WvP
__device__ float g_M2f[NTOT];           // WkP^T @ T1cat (only diag blocks meaningful)
__device__ float g_M2b[NTOT];           // block-diagonal masked M2
__device__ float g_C2 [NTOT];           // WqT^T @ M2bd
__device__ float g_R  [NTOT];           // C2 @ Wo_flat
__device__ float g_WvP[SZ];             // WvP[j][h*64+v] = Wv[h][j][v]
__device__ float g_WkP[SZ];             // WkP[j][h*64+k'] = Wk[h][j][k']
__device__ float g_WqT[SZ];             // WqT[h*64+k'][i] = Wq[h][i][k']

// ---------------- 128x128 tile SGEMM, f32x2 packed, 8x8 microtile ----------
// TRANSA=true : A stored K x M (row k contiguous in m)
// TRANSA=false: A stored M x K (row m contiguous in k)
// B always K x N. C row-major M x N.
template<bool TRANSA>
__device__ __forceinline__ void gemm128(
    const float* __restrict__ A, const float* __restrict__ B,
    float* __restrict__ C,
    int lda, int ldb, int ldc,
    int m0, int n0, int kbeg, int kend)
{
    __shared__ float As[16][132];   // pad keeps 16B row alignment (132*4=528)
    __shared__ float Bs[16][128];

    const int tid = threadIdx.x;
    const int tx = tid & 15;        // n-group (8 cols each)
    const int ty = tid >> 4;        // m-group (8 rows each)

    unsigned long long acc[8][4];   // packed {f32,f32} pairs along n
#pragma unroll
    for (int i = 0; i < 8; i++)
#pragma unroll
        for (int j = 0; j < 4; j++) acc[i][j] = 0ull;

    for (int kb = kbeg; kb < kend; kb += 16) {
#pragma unroll
        for (int i = 0; i < 2; i++) {
            int lin = tid + i * 256;            // 0..511
            if (TRANSA) {
                int kk = lin >> 5, m4 = (lin & 31) << 2;
                *(float4*)&As[kk][m4] =
                    *(const float4*)&A[(long)(kb + kk) * lda + m0 + m4];
            } else {
                int mm = lin >> 2, k4 = (lin & 3) << 2;
                float4 v = *(const float4*)&A[(long)(m0 + mm) * lda + kb + k4];
                As[k4 + 0][mm] = v.x; As[k4 + 1][mm] = v.y;
                As[k4 + 2][mm] = v.z; As[k4 + 3][mm] = v.w;
            }
            int kk = lin >> 5, n4 = (lin & 31) << 2;
            *(float4*)&Bs[kk][n4] =
                *(const float4*)&B[(long)(kb + kk) * ldb + n0 + n4];
        }
        __syncthreads();

#pragma unroll
        for (int kk = 0; kk < 16; kk++) {
            float4 a0 = *(const float4*)&As[kk][ty * 8];
            float4 a1 = *(const float4*)&As[kk][ty * 8 + 4];
            ulonglong2 bq0 = *(const ulonglong2*)&Bs[kk][tx * 8];
            ulonglong2 bq1 = *(const ulonglong2*)&Bs[kk][tx * 8 + 4];
            unsigned long long bp[4] = {bq0.x, bq0.y, bq1.x, bq1.y};
            float av[8] = {a0.x, a0.y, a0.z, a0.w, a1.x, a1.y, a1.z, a1.w};
#pragma unroll
            for (int i = 0; i < 8; i++) {
                unsigned long long ap;
                asm("mov.b64 %0, {%1, %1};" : "=l"(ap) : "f"(av[i]));
#pragma unroll
                for (int j = 0; j < 4; j++)
                    asm("fma.rn.f32x2 %0, %1, %2, %0;"
                        : "+l"(acc[i][j]) : "l"(ap), "l"(bp[j]));
            }
        }
        __syncthreads();
    }

#pragma unroll
    for (int i = 0; i < 8; i++) {
        long row = (long)(m0 + ty * 8 + i) * ldc + n0 + tx * 8;
        *(ulonglong2*)&C[row]     = make_ulonglong2(acc[i][0], acc[i][1]);
        *(ulonglong2*)&C[row + 4] = make_ulonglong2(acc[i][2], acc[i][3]);
    }
}

// ---------------- stage wrappers ----------------

// gram partials: Gp[z] = X_b[chunk]^T X_b[chunk], z = c*B + b
__global__ __launch_bounds__(256, 2) void k_gram(const float* __restrict__ x)
{
    int z = blockIdx.z, b = z % B_, c = z / B_;
    const float* X = x + (long)b * L_ * DIN;
    gemm128<true>(X, X, g_Gp + (long)z * SZ, DIN, DIN, 512,
                  blockIdx.x * 128, blockIdx.y * 128,
                  c * (L_ / NCH_G), (c + 1) * (L_ / NCH_G));
}

// split-K reduction. Pointers resolved IN DEVICE CODE (passing __device__
// symbols as host-side kernel args is invalid — that was the R1 bug).
__global__ void k_reduce(int srcsel, int dstsel, int nch)
{
    const float* src = (srcsel == 0) ? g_Gp : g_Pb;
    float* dst;
    switch (dstsel) {
        case 0: dst = g_G;   break;
        case 1: dst = g_T1;  break;
        case 2: dst = g_M2f; break;
        case 3: dst = g_C2;  break;
        default: dst = g_R;  break;
    }
    long i4 = (long)blockIdx.x * blockDim.x + threadIdx.x;   // float4 index
    long off = i4 * 4;
    float4 s = make_float4(0.f, 0.f, 0.f, 0.f);
    for (int c = 0; c < nch; c++) {
        float4 v = *(const float4*)&src[(long)c * NTOT + off];
        s.x += v.x; s.y += v.y; s.z += v.z; s.w += v.w;
    }
    *(float4*)&dst[off] = s;
}

// weight permutations (all three in one pass)
__global__ void k_perm(const float* __restrict__ Wq, const float* __restrict__ Wk,
                       const float* __restrict__ Wv)
{
    int i = blockIdx.x * 256 + threadIdx.x;     // 0 .. 8*512*64-1
    int h = i >> 15;            // / (512*64)
    int j = (i >> 6) & 511;
    int c = i & 63;
    int col = h * 64 + c;
    g_WvP[j * 512 + col] = Wv[i];
    g_WkP[j * 512 + col] = Wk[i];
    g_WqT[col * 512 + j] = Wq[i];
}

// middle GEMM wrappers, all split-K NCH_M over K=512, z = c*B + b
__global__ __launch_bounds__(256, 2) void k_t1p()
{
    int z = blockIdx.z, b = z % B_, c = z / B_;
    gemm128<true>(g_G + (long)b * SZ, g_WvP, g_Pb + (long)z * SZ, 512, 512, 512,
                  blockIdx.x * 128, blockIdx.y * 128,
                  c * (512 / NCH_M), (c + 1) * (512 / NCH_M));
}
__global__ __launch_bounds__(256, 2) void k_m2p()
{
    int z = blockIdx.z, b = z % B_, c = z / B_;
    gemm128<true>(g_WkP, g_T1 + (long)b * SZ, g_Pb + (long)z * SZ, 512, 512, 512,
                  blockIdx.x * 128, blockIdx.y * 128,
                  c * (512 / NCH_M), (c + 1) * (512 / NCH_M));
}
// block-diagonal mask: keep M2f[b][r][c] only where r,c in same 64-block
__global__ void k_bd()
{
    long i4 = (long)blockIdx.x * blockDim.x + threadIdx.x;
    long off = i4 * 4;
    int ccol = (int)(off & 511);
    int rrow = (int)((off >> 9) & 511);
    float4 v = *(const float4*)&g_M2f[off];
    if ((rrow >> 6) != (ccol >> 6)) v = make_float4(0.f, 0.f, 0.f, 0.f);
    *(float4*)&g_M2b[off] = v;
}
__global__ __launch_bounds__(256, 2) void k_c2p()
{
    int z = blockIdx.z, b = z % B_, c = z / B_;
    gemm128<true>(g_WqT, g_M2b + (long)b * SZ, g_Pb + (long)z * SZ, 512, 512, 512,
                  blockIdx.x * 128, blockIdx.y * 128,
                  c * (512 / NCH_M), (c + 1) * (512 / NCH_M));
}
__global__ __launch_bounds__(256, 2) void k_rp(const float* __restrict__ Wo)
{
    int z = blockIdx.z, b = z % B_, c = z / B_;
    gemm128<false>(g_C2 + (long)b * SZ, Wo, g_Pb + (long)z * SZ, 512, 512, 512,
                   blockIdx.x * 128, blockIdx.y * 128,
                   c * (512 / NCH_M), (c + 1) * (512 / NCH_M));
}

// out_b = X_b @ R_b  (4096x512, K=512, no split)
__global__ __launch_bounds__(256, 2) void k_out(const float* __restrict__ x,
                                                float* __restrict__ out)
{
    int b = blockIdx.z;
    gemm128<false>(x + (long)b * L_ * DIN, g_R + (long)b * SZ,
                   out + (long)b * L_ * DOUT, DIN, 512, DOUT,
                   blockIdx.x * 128, blockIdx.y * 128, 0, 512);
}

// ---------------- launch ----------------
extern "C" void kernel_launch(void* const* d_in, const int* in_sizes, int n_in,
                              void* d_out, int out_size)
{
    const float* x  = (const float*)d_in[0];
    const float* Wq = (const float*)d_in[1];
    const float* Wk = (const float*)d_in[2];
    const float* Wv = (const float*)d_in[3];
    const float* Wo = (const float*)d_in[4];
    float* out = (float*)d_out;

    const int R4 = NTOT / 4 / 256;   // reduce grid: 512 blocks of 256 (float4)

    k_perm  <<<(H_ * DIN * DK) / 256, 256>>>(Wq, Wk, Wv);
    k_gram  <<<dim3(4, 4, B_ * NCH_G), 256>>>(x);
    k_reduce<<<R4, 256>>>(0, 0, NCH_G);      // g_Gp -> g_G

    k_t1p   <<<dim3(4, 4, B_ * NCH_M), 256>>>();
    k_reduce<<<R4, 256>>>(1, 1, NCH_M);      // g_Pb -> g_T1

    k_m2p   <<<dim3(4, 4, B_ * NCH_M), 256>>>();
    k_reduce<<<R4, 256>>>(1, 2, NCH_M);      // g_Pb -> g_M2f
    k_bd    <<<R4, 256>>>();

    k_c2p   <<<dim3(4, 4, B_ * NCH_M), 256>>>();
    k_reduce<<<R4, 256>>>(1, 3, NCH_M);      // g_Pb -> g_C2

    k_rp    <<<dim3(4, 4, B_ * NCH_M), 256>>>(Wo);
    k_reduce<<<R4, 256>>>(1, 4, NCH_M);      // g_Pb -> g_R

    k_out   <<<dim3(32, 4, B_), 256>>>(x, out);
}